// round 16
// baseline (speedup 1.0000x reference)
#include <cuda_runtime.h>

typedef unsigned long long u64;
typedef unsigned int u32;

__device__ __forceinline__ u64 pack2(float lo, float hi) {
    u64 r; asm("mov.b64 %0,{%1,%2};" : "=l"(r) : "f"(lo), "f"(hi)); return r;
}
__device__ __forceinline__ void unpack2(u64 v, float& lo, float& hi) {
    asm("mov.b64 {%0,%1}, %2;" : "=f"(lo), "=f"(hi) : "l"(v));
}
__device__ __forceinline__ u64 fma2(u64 a, u64 b, u64 c) {
    u64 d; asm("fma.rn.f32x2 %0,%1,%2,%3;" : "=l"(d) : "l"(a), "l"(b), "l"(c)); return d;
}
__device__ __forceinline__ u64 add2(u64 a, u64 b) {
    u64 d; asm("add.rn.f32x2 %0,%1,%2;" : "=l"(d) : "l"(a), "l"(b)); return d;
}
__device__ __forceinline__ u64 mul2(u64 a, u64 b) {
    u64 d; asm("mul.rn.f32x2 %0,%1,%2;" : "=l"(d) : "l"(a), "l"(b)); return d;
}
__device__ __forceinline__ float sqrt_approx(float x) {
    float r; asm("sqrt.approx.f32 %0, %1;" : "=f"(r) : "f"(x)); return r;
}
// relu both halves of a packed f32x2 (2 scalar FMNMX, alu pipe)
__device__ __forceinline__ u64 relu2(u64 v) {
    float lo, hi; unpack2(v, lo, hi);
    return pack2(fmaxf(lo, 0.f), fmaxf(hi, 0.f));
}

constexpr int NE = 7;      // entities
constexpr int DE = 4;      // dims per entity
constexpr int H  = 128;    // half embedding
constexpr int NPAIR = 21;  // unordered pairs
constexpr int OUTC = 2 * H;
constexpr int ROW = NE * OUTC;   // floats per batch element in out
constexpr int GRID = 592;        // 148 SMs x 4 resident CTAs = one wave

// pair index tables packed 3 bits/entry into u64 immediates (device-legal)
constexpr u64 pack_idx(const int* a) {
    u64 r = 0;
    for (int p = 0; p < NPAIR; p++) r |= (u64)a[p] << (3 * p);
    return r;
}
constexpr int PIa_host[NPAIR] = {0,0,0,0,0,0,1,1,1,1,1,2,2,2,2,3,3,3,4,4,5};
constexpr int PJa_host[NPAIR] = {1,2,3,4,5,6,2,3,4,5,6,3,4,5,6,4,5,6,5,6,6};
constexpr u64 PIp = pack_idx(PIa_host);
constexpr u64 PJp = pack_idx(PJa_host);

__global__ __launch_bounds__(256, 4)
void enc_kernel(const float* __restrict__ ctx,
                const float* __restrict__ w_prop, const float* __restrict__ b_prop,
                const float* __restrict__ w_rel,  const float* __restrict__ b_rel,
                float* __restrict__ out, int B, int G)
{
    constexpr int PI[NPAIR] = {0,0,0,0,0,0,1,1,1,1,1,2,2,2,2,3,3,3,4,4,5};
    constexpr int PJ[NPAIR] = {1,2,3,4,5,6,2,3,4,5,6,3,4,5,6,4,5,6,5,6,6};

    // two 128-thread sub-blocks per CTA, each owning 2 batches.
    // entity/dist values stored BROADCAST-packed (v,v) per batch so stage 3
    // can feed fma.rn.f32x2 over an h-pair. Double-buffered: 1 barrier/iter.
    __shared__ __align__(16) u64 sh_ents[2][2][2][NE * DE]; // [par][sub][batch][row]
    __shared__ __align__(16) u64 sh_dist[2][2][2][22];      // 22 = 16B-align pad

    const int tid  = threadIdx.x;
    const int lane = tid & 31;
    const int wid  = tid >> 5;
    const int s    = wid >> 2;            // sub-block 0/1
    const int bar  = s + 1;               // named barrier id
    const int wrole = wid & 3;            // 0: ents loader, 1: dist builder
    const bool w0  = wrole == 0;
    const bool w1  = wrole == 1;
    const int bsel = (tid >> 6) & 1;      // stage-3: which batch of the pair
    const int h0   = (tid & 63) * 2;      // stage-3: h-pair {h0, h0+1}

    // weights as natural float2 over {h0, h0+1} — loaded once per CTA
    u64 wp2[DE], wr2[DE + 1], bp2, br2;
    #pragma unroll
    for (int d = 0; d < DE; d++)     { float2 w = *(const float2*)(w_prop + d * H + h0); wp2[d] = pack2(w.x, w.y); }
    #pragma unroll
    for (int d = 0; d < DE + 1; d++) { float2 w = *(const float2*)(w_rel  + d * H + h0); wr2[d] = pack2(w.x, w.y); }
    { float2 v = *(const float2*)(b_prop + h0); bp2 = pack2(v.x, v.y); }
    { float2 v = *(const float2*)(b_rel  + h0); br2 = pack2(v.x, v.y); }
    const u64 neg1 = pack2(-1.f, -1.f);

    // w1 dist-lane pair row indices (lanes 0..20)
    const int li4 = (int)((PIp >> (3 * lane)) & 7) * DE;
    const int lj4 = (int)((PJp >> (3 * lane)) & 7) * DE;

    // w0 prefetch of first group's ctx rows (lanes 0..27), float2 {b0, b0+1}
    int g = blockIdx.x;
    float2 v = make_float2(0.f, 0.f);
    if (w0 && lane < NE * DE && g < G)
        v = *(const float2*)(ctx + lane * B + (g * 4 + s * 2));

    int par = 0;
    for (; g < G; g += GRID) {
        const int b0 = g * 4 + s * 2;
        const float* cb = ctx + b0;

        if (w0) {
            // commit prefetched rows broadcast-packed per batch; prefetch next
            if (lane < NE * DE) {
                sh_ents[par][s][0][lane] = pack2(v.x, v.x);
                sh_ents[par][s][1][lane] = pack2(v.y, v.y);
            }
            const int gn = g + GRID;
            if (lane < NE * DE && gn < G)
                v = *(const float2*)(ctx + lane * B + (gn * 4 + s * 2));
        } else if (w1 && lane < NPAIR) {
            // dist builder: rows are L1-hits (w0 prefetched these lines last iter)
            float2 xi = *(const float2*)(cb + (li4    ) * B);
            float2 yi = *(const float2*)(cb + (li4 + 1) * B);
            float2 xj = *(const float2*)(cb + (lj4    ) * B);
            float2 yj = *(const float2*)(cb + (lj4 + 1) * B);
            float dxl = xi.x - xj.x, dyl = yi.x - yj.x;
            float dxh = xi.y - xj.y, dyh = yi.y - yj.y;
            float dl = sqrt_approx(dxl*dxl + dyl*dyl);
            float dh = sqrt_approx(dxh*dxh + dyh*dyh);
            sh_dist[par][s][0][lane] = pack2(dl, dl);
            sh_dist[par][s][1][lane] = pack2(dh, dh);
        }
        asm volatile("bar.sync %0, 128;" :: "r"(bar) : "memory");

        // ---- stage 3: one batch, one h-pair per thread; STG.64 outputs ----
        float* outp = out + (size_t)(b0 + bsel) * ROW + h0;

        u64 qd[NE];
        const ulonglong2* e4 = (const ulonglong2*)sh_ents[par][s][bsel];
        #pragma unroll
        for (int e = 0; e < NE; e++) {
            ulonglong2 q0 = e4[e*2 + 0];   // d0, d1 (broadcast-packed)
            ulonglong2 q1 = e4[e*2 + 1];   // d2, d3
            u64 acc = fma2(q0.x, wp2[0], bp2);
            acc = fma2(q0.y, wp2[1], acc);
            acc = fma2(q1.x, wp2[2], acc);
            acc = fma2(q1.y, wp2[3], acc);
            *(u64*)(outp + e * OUTC) = relu2(acc);      // STG.64, packed
            u64 q = mul2(q0.x, wr2[0]);
            q = fma2(q0.y, wr2[1], q);
            q = fma2(q1.x, wr2[2], q);
            q = fma2(q1.y, wr2[3], q);
            qd[e] = q;
        }

        // relation embedding; first-touch init avoids zeroing racc
        u64 racc[NE];
        const u64* db = sh_dist[par][s][bsel];

        auto do_pair = [&](int p, u64 dist) {
            const int i = PI[p], j = PJ[p];
            u64 sb = fma2(dist, wr2[4], br2);    // symmetric part
            u64 sd = fma2(qd[j], neg1, qd[i]);   // q_i - q_j
            u64 rij = relu2(add2(sb, sd));       // relu(sb + sd)
            u64 rji = relu2(fma2(sd, neg1, sb)); // relu(sb - sd)
            if (p == 0) racc[i] = rij; else racc[i] = add2(racc[i], rij);
            if (p <= 5) racc[j] = rji; else racc[j] = add2(racc[j], rji);
        };

        #pragma unroll
        for (int pp = 0; pp < 20; pp += 2) {
            ulonglong2 dd = *(const ulonglong2*)(db + pp);   // LDS.128
            do_pair(pp,     dd.x);
            do_pair(pp + 1, dd.y);
        }
        do_pair(20, db[20]);

        #pragma unroll
        for (int e = 0; e < NE; e++) {
            *(u64*)(outp + e * OUTC + H) = racc[e];          // STG.64, packed
        }

        par ^= 1;   // double-buffer flip: no trailing WAR barrier needed
    }
}

extern "C" void kernel_launch(void* const* d_in, const int* in_sizes, int n_in,
                              void* d_out, int out_size) {
    const float* ctx    = (const float*)d_in[0];
    const float* w_prop = (const float*)d_in[1];
    const float* b_prop = (const float*)d_in[2];
    const float* w_rel  = (const float*)d_in[3];
    const float* b_rel  = (const float*)d_in[4];
    float* out = (float*)d_out;

    const int B = in_sizes[0] / (NE * DE);   // 16384
    const int G = B / 4;                     // 4096 groups of 4 batches
    enc_kernel<<<GRID, 256>>>(ctx, w_prop, b_prop, w_rel, b_rel, out, B, G);
}

// round 17
// speedup vs baseline: 1.1517x; 1.1517x over previous
#include <cuda_runtime.h>

typedef unsigned long long u64;
typedef unsigned int u32;

__device__ __forceinline__ u64 pack2(float lo, float hi) {
    u64 r; asm("mov.b64 %0,{%1,%2};" : "=l"(r) : "f"(lo), "f"(hi)); return r;
}
__device__ __forceinline__ void unpack2(u64 v, float& lo, float& hi) {
    asm("mov.b64 {%0,%1}, %2;" : "=f"(lo), "=f"(hi) : "l"(v));
}
__device__ __forceinline__ u64 fma2(u64 a, u64 b, u64 c) {
    u64 d; asm("fma.rn.f32x2 %0,%1,%2,%3;" : "=l"(d) : "l"(a), "l"(b), "l"(c)); return d;
}
__device__ __forceinline__ u64 add2(u64 a, u64 b) {
    u64 d; asm("add.rn.f32x2 %0,%1,%2;" : "=l"(d) : "l"(a), "l"(b)); return d;
}
__device__ __forceinline__ u64 mul2(u64 a, u64 b) {
    u64 d; asm("mul.rn.f32x2 %0,%1,%2;" : "=l"(d) : "l"(a), "l"(b)); return d;
}
__device__ __forceinline__ float sqrt_approx(float x) {
    float r; asm("sqrt.approx.f32 %0, %1;" : "=f"(r) : "f"(x)); return r;
}
// relu both halves of a packed f32x2 (2 scalar FMNMX, alu pipe)
__device__ __forceinline__ u64 relu2(u64 v) {
    float lo, hi; unpack2(v, lo, hi);
    return pack2(fmaxf(lo, 0.f), fmaxf(hi, 0.f));
}

constexpr int NE = 7;      // entities
constexpr int DE = 4;      // dims per entity
constexpr int H  = 128;    // half embedding
constexpr int NPAIR = 21;  // unordered pairs
constexpr int OUTC = 2 * H;
constexpr int ROW = NE * OUTC;   // floats per batch element in out
constexpr int GRID = 592;        // 148 SMs x 4 resident CTAs = one wave

// pair index tables packed 3 bits/entry into u64 immediates (device-legal)
constexpr u64 pack_idx(const int* a) {
    u64 r = 0;
    for (int p = 0; p < NPAIR; p++) r |= (u64)a[p] << (3 * p);
    return r;
}
constexpr int PIa_host[NPAIR] = {0,0,0,0,0,0,1,1,1,1,1,2,2,2,2,3,3,3,4,4,5};
constexpr int PJa_host[NPAIR] = {1,2,3,4,5,6,2,3,4,5,6,3,4,5,6,4,5,6,5,6,6};
constexpr u64 PIp = pack_idx(PIa_host);
constexpr u64 PJp = pack_idx(PJa_host);

__global__ __launch_bounds__(256, 4)
void enc_kernel(const float* __restrict__ ctx,
                const float* __restrict__ w_prop, const float* __restrict__ b_prop,
                const float* __restrict__ w_rel,  const float* __restrict__ b_rel,
                float* __restrict__ out, int B, int G)
{
    constexpr int PI[NPAIR] = {0,0,0,0,0,0,1,1,1,1,1,2,2,2,2,3,3,3,4,4,5};
    constexpr int PJ[NPAIR] = {1,2,3,4,5,6,2,3,4,5,6,3,4,5,6,4,5,6,5,6,6};

    // two 128-thread sub-blocks per CTA; DOUBLE-BUFFERED shared state so
    // one barrier per iteration suffices. sh_dist padded to 22 for 16B align.
    __shared__ __align__(16) u64 sh_ents[2][2][NE * DE];  // [parity][sub][row]
    __shared__ __align__(16) u64 sh_dist[2][2][22];

    const int tid  = threadIdx.x;
    const int lane = tid & 31;
    const int wid  = tid >> 5;
    const int s    = wid >> 2;           // sub-block 0/1
    const int h    = tid & 127;          // output column 0..127
    const int bar  = s + 1;              // named barrier id
    const int wrole = wid & 3;           // 0: ents loader, 1: dist builder
    const bool w0  = wrole == 0;
    const bool w1  = wrole == 1;

    // weights broadcast-packed once per CTA
    u64 wp2[DE], wr2[DE + 1], bp2, br2;
    #pragma unroll
    for (int d = 0; d < DE; d++)     { float w = w_prop[d * H + h]; wp2[d] = pack2(w, w); }
    #pragma unroll
    for (int d = 0; d < DE + 1; d++) { float w = w_rel [d * H + h]; wr2[d] = pack2(w, w); }
    { float b = b_prop[h]; bp2 = pack2(b, b); }
    { float b = b_rel [h]; br2 = pack2(b, b); }
    const u64 neg1 = pack2(-1.f, -1.f);

    // w1 dist-lane pair row indices (lanes 0..20)
    const int li4 = (int)((PIp >> (3 * lane)) & 7) * DE;
    const int lj4 = (int)((PJp >> (3 * lane)) & 7) * DE;

    // w0 prefetch of first group's ctx rows (lanes 0..27)
    int g0 = blockIdx.x;
    float2 v = make_float2(0.f, 0.f);
    if (w0 && lane < NE * DE && g0 < G)
        v = *(const float2*)(ctx + lane * B + (g0 * 4 + s * 2));

    // one iteration body; `par` is always a compile-time literal at the call
    // sites so all shared addressing folds to immediate offsets.
    auto body = [&](int g, int par) __attribute__((always_inline)) {
        const int b0 = g * 4 + s * 2;
        const float* cb = ctx + b0;

        if (w0) {
            // commit prefetched ctx rows; prefetch the NEXT group (g + GRID)
            if (lane < NE * DE) sh_ents[par][s][lane] = pack2(v.x, v.y);
            const int gn = g + GRID;
            if (lane < NE * DE && gn < G)
                v = *(const float2*)(ctx + lane * B + (gn * 4 + s * 2));
        } else if (w1 && lane < NPAIR) {
            // dist builder: 4 coord rows are L1-hits (w0 prefetched the lines)
            float2 xi = *(const float2*)(cb + (li4    ) * B);
            float2 yi = *(const float2*)(cb + (li4 + 1) * B);
            float2 xj = *(const float2*)(cb + (lj4    ) * B);
            float2 yj = *(const float2*)(cb + (lj4 + 1) * B);
            float dxl = xi.x - xj.x, dyl = yi.x - yj.x;
            float dxh = xi.y - xj.y, dyh = yi.y - yj.y;
            sh_dist[par][s][lane] = pack2(sqrt_approx(dxl*dxl + dyl*dyl),
                                          sqrt_approx(dxh*dxh + dyh*dyh));
        }
        asm volatile("bar.sync %0, 128;" :: "r"(bar) : "memory");

        // ---- stage 3: packed-f32x2 compute, one h per thread ----
        float* out0 = out + (size_t)b0 * ROW;
        float* out1 = out0 + ROW;     // batch b0+1

        u64 qd[NE];
        const ulonglong2* e4 = (const ulonglong2*)sh_ents[par][s];
        #pragma unroll
        for (int e = 0; e < NE; e++) {
            ulonglong2 q0 = e4[e*2 + 0];   // d0, d1 (packed over 2 batches)
            ulonglong2 q1 = e4[e*2 + 1];   // d2, d3
            u64 acc = fma2(q0.x, wp2[0], bp2);
            acc = fma2(q0.y, wp2[1], acc);
            acc = fma2(q1.x, wp2[2], acc);
            acc = fma2(q1.y, wp2[3], acc);
            float lo, hi; unpack2(acc, lo, hi);
            out0[e * OUTC + h] = fmaxf(lo, 0.f);
            out1[e * OUTC + h] = fmaxf(hi, 0.f);
            u64 q = mul2(q0.x, wr2[0]);
            q = fma2(q0.y, wr2[1], q);
            q = fma2(q1.x, wr2[2], q);
            q = fma2(q1.y, wr2[3], q);
            qd[e] = q;
        }

        // relation embedding; first-touch init avoids zeroing racc
        u64 racc[NE];
        const u64* db = sh_dist[par][s];

        auto do_pair = [&](int p, u64 dist) {
            const int i = PI[p], j = PJ[p];
            u64 sb = fma2(dist, wr2[4], br2);    // symmetric part
            u64 sd = fma2(qd[j], neg1, qd[i]);   // q_i - q_j
            u64 rij = relu2(add2(sb, sd));       // relu(sb + sd)
            u64 rji = relu2(fma2(sd, neg1, sb)); // relu(sb - sd)
            if (p == 0) racc[i] = rij; else racc[i] = add2(racc[i], rij);
            if (p <= 5) racc[j] = rji; else racc[j] = add2(racc[j], rji);
        };

        #pragma unroll
        for (int pp = 0; pp < 20; pp += 2) {
            ulonglong2 dd = *(const ulonglong2*)(db + pp);   // LDS.128
            do_pair(pp,     dd.x);
            do_pair(pp + 1, dd.y);
        }
        do_pair(20, db[20]);

        #pragma unroll
        for (int e = 0; e < NE; e++) {
            float lo, hi; unpack2(racc[e], lo, hi);
            out0[e * OUTC + H + h] = lo;
            out1[e * OUTC + H + h] = hi;
        }
    };

    // unroll-by-2: parity is a literal in each body -> immediate shared offsets
    for (int g = g0; g < G; g += 2 * GRID) {
        body(g, 0);
        if (g + GRID < G) body(g + GRID, 1);
    }
}

extern "C" void kernel_launch(void* const* d_in, const int* in_sizes, int n_in,
                              void* d_out, int out_size) {
    const float* ctx    = (const float*)d_in[0];
    const float* w_prop = (const float*)d_in[1];
    const float* b_prop = (const float*)d_in[2];
    const float* w_rel  = (const float*)d_in[3];
    const float* b_rel  = (const float*)d_in[4];
    float* out = (float*)d_out;

    const int B = in_sizes[0] / (NE * DE);   // 16384
    const int G = B / 4;                     // 4096 groups of 4 batches
    enc_kernel<<<GRID, 256>>>(ctx, w_prop, b_prop, w_rel, b_rel, out, B, G);
}